// round 2
// baseline (speedup 1.0000x reference)
#include <cuda_runtime.h>
#include <math.h>

// ---------------- problem-size constants (from setup_inputs) ----------------
#define MAXN 100000
#define MAXE 1200000
#define F_IN  64
#define F_HID 64
#define F_OUT 16

// ---------------- device scratch (no allocations allowed) ----------------
__device__ float g_y[MAXN * F_HID];      // x @ W1
__device__ float g_aggr1[MAXN * F_HID];  // scatter target, layer 1
__device__ float g_h[MAXN * F_HID];      // relu(aggr + self + b1)
__device__ float g_z[MAXN * F_OUT];      // h @ W2
__device__ float g_aggr2[MAXN * F_OUT];  // scatter target, layer 2
__device__ int   g_deg[MAXN];
__device__ float g_dinv[MAXN];
__device__ int   g_rows[MAXE];
__device__ int   g_cols[MAXE];
__device__ float g_coef[MAXE];

// ---------------- kernels ----------------

// Zero all accumulators + degree counters (must run every launch: graph replays).
__global__ void init_kernel(int N) {
    int idx = blockIdx.x * blockDim.x + threadIdx.x;
    int total = N * (F_HID / 4);           // N*16 float4 = N*64 floats
    if (idx < total)      reinterpret_cast<float4*>(g_aggr1)[idx] = make_float4(0.f, 0.f, 0.f, 0.f);
    if (idx < N * (F_OUT / 4)) reinterpret_cast<float4*>(g_aggr2)[idx] = make_float4(0.f, 0.f, 0.f, 0.f);
    if (idx < N)          g_deg[idx] = 0;
}

// deg[i] = #edges with row==i  (self loop added later as +1)
__global__ void deg_kernel(const int* __restrict__ ei, int E) {
    int e = blockIdx.x * blockDim.x + threadIdx.x;
    if (e < E) atomicAdd(&g_deg[ei[e]], 1);
}

__global__ void dinv_kernel(int N) {
    int i = blockIdx.x * blockDim.x + threadIdx.x;
    if (i < N) g_dinv[i] = rsqrtf((float)(g_deg[i] + 1));
}

// Precompute row/col and per-edge normalization coefficient.
__global__ void edgeprep_kernel(const int* __restrict__ ei, int E) {
    int e = blockIdx.x * blockDim.x + threadIdx.x;
    if (e < E) {
        int r = ei[e];
        int c = ei[E + e];
        g_rows[e] = r;
        g_cols[e] = c;
        g_coef[e] = g_dinv[r] * g_dinv[c];
    }
}

// y = x @ W1   ([N,64] @ [64,64])
// block: 64x4 threads, 16 rows per block, each thread computes 4 rows x 1 col
__global__ __launch_bounds__(256) void gemm1_kernel(const float* __restrict__ x,
                                                    const float* __restrict__ W,
                                                    int N) {
    __shared__ float Ws[64 * 64];
    __shared__ float xs[16 * 64];
    int tx = threadIdx.x;           // 0..63 (output column)
    int ty = threadIdx.y;           // 0..3
    int tid = ty * 64 + tx;

    for (int i = tid; i < 64 * 64; i += 256) Ws[i] = W[i];

    int row0 = blockIdx.x * 16;
    // load 16 rows of x as float4 (16*16 = 256 float4)
    {
        int r  = tid >> 4;          // 0..15
        int cc = tid & 15;          // 0..15 float4 within row
        int gr = row0 + r;
        float4 v = (gr < N) ? reinterpret_cast<const float4*>(x)[(size_t)gr * 16 + cc]
                            : make_float4(0.f, 0.f, 0.f, 0.f);
        reinterpret_cast<float4*>(xs)[r * 16 + cc] = v;
    }
    __syncthreads();

    float acc[4] = {0.f, 0.f, 0.f, 0.f};
#pragma unroll
    for (int k = 0; k < 64; k++) {
        float w = Ws[k * 64 + tx];
#pragma unroll
        for (int r = 0; r < 4; r++) acc[r] += xs[(ty * 4 + r) * 64 + k] * w;
    }
#pragma unroll
    for (int r = 0; r < 4; r++) {
        int gr = row0 + ty * 4 + r;
        if (gr < N) g_y[(size_t)gr * 64 + tx] = acc[r];
    }
}

// Layer-1 edge scatter: 16 lanes per edge, each does one float4 gather + vec4 red.
__global__ __launch_bounds__(256) void scatter1_kernel(int E) {
    long long t = (long long)blockIdx.x * blockDim.x + threadIdx.x;
    int e = (int)(t >> 4);
    if (e >= E) return;
    int q = (int)t & 15;
    int r = g_rows[e];
    int c = g_cols[e];
    float coef = g_coef[e];
    float4 v = reinterpret_cast<const float4*>(g_y)[(size_t)r * 16 + q];
    float4 m = make_float4(v.x * coef, v.y * coef, v.z * coef, v.w * coef);
    float* dst = &g_aggr1[(size_t)c * 64 + q * 4];
    asm volatile("red.global.add.v4.f32 [%0], {%1,%2,%3,%4};"
                 :: "l"(dst), "f"(m.x), "f"(m.y), "f"(m.z), "f"(m.w) : "memory");
}

// h = relu(aggr1 + dinv^2 * y + b1)
__global__ __launch_bounds__(256) void epi1_kernel(const float* __restrict__ b1, int N) {
    int idx = blockIdx.x * blockDim.x + threadIdx.x;   // over N*16 float4
    if (idx >= N * 16) return;
    int i = idx >> 4;
    int q = idx & 15;
    float di = g_dinv[i];
    float s = di * di;
    float4 a  = reinterpret_cast<const float4*>(g_aggr1)[idx];
    float4 yv = reinterpret_cast<const float4*>(g_y)[idx];
    float4 bb = reinterpret_cast<const float4*>(b1)[q];
    float4 hv;
    hv.x = fmaxf(a.x + s * yv.x + bb.x, 0.f);
    hv.y = fmaxf(a.y + s * yv.y + bb.y, 0.f);
    hv.z = fmaxf(a.z + s * yv.z + bb.z, 0.f);
    hv.w = fmaxf(a.w + s * yv.w + bb.w, 0.f);
    reinterpret_cast<float4*>(g_h)[idx] = hv;
}

// z = h @ W2   ([N,64] @ [64,16])
// block: 16x16 threads, 16 rows per block, 1 output per thread
__global__ __launch_bounds__(256) void gemm2_kernel(const float* __restrict__ W, int N) {
    __shared__ float Ws[64 * 16];
    __shared__ float hs[16 * 64];
    int tx = threadIdx.x;   // 0..15 output column
    int ty = threadIdx.y;   // 0..15 row in tile
    int tid = ty * 16 + tx;

    for (int i = tid; i < 64 * 16; i += 256) Ws[i] = W[i];

    int row0 = blockIdx.x * 16;
    {
        int r  = tid >> 4;
        int cc = tid & 15;
        int gr = row0 + r;
        float4 v = (gr < N) ? reinterpret_cast<const float4*>(g_h)[(size_t)gr * 16 + cc]
                            : make_float4(0.f, 0.f, 0.f, 0.f);
        reinterpret_cast<float4*>(hs)[r * 16 + cc] = v;
    }
    __syncthreads();

    float acc = 0.f;
#pragma unroll
    for (int k = 0; k < 64; k++) acc += hs[ty * 64 + k] * Ws[k * 16 + tx];

    int gr = row0 + ty;
    if (gr < N) g_z[(size_t)gr * 16 + tx] = acc;
}

// Layer-2 edge scatter: 4 lanes per edge (16 floats = 4 float4).
__global__ __launch_bounds__(256) void scatter2_kernel(int E) {
    long long t = (long long)blockIdx.x * blockDim.x + threadIdx.x;
    int e = (int)(t >> 2);
    if (e >= E) return;
    int q = (int)t & 3;
    int r = g_rows[e];
    int c = g_cols[e];
    float coef = g_coef[e];
    float4 v = reinterpret_cast<const float4*>(g_z)[(size_t)r * 4 + q];
    float4 m = make_float4(v.x * coef, v.y * coef, v.z * coef, v.w * coef);
    float* dst = &g_aggr2[(size_t)c * 16 + q * 4];
    asm volatile("red.global.add.v4.f32 [%0], {%1,%2,%3,%4};"
                 :: "l"(dst), "f"(m.x), "f"(m.y), "f"(m.z), "f"(m.w) : "memory");
}

// logits = aggr2 + dinv^2*z + b2; out = log_softmax(logits)
__global__ __launch_bounds__(256) void epi2_kernel(const float* __restrict__ b2,
                                                   float* __restrict__ out, int N) {
    int i = blockIdx.x * blockDim.x + threadIdx.x;
    if (i >= N) return;
    float di = g_dinv[i];
    float s = di * di;
    float l[16];
#pragma unroll
    for (int q = 0; q < 4; q++) {
        float4 a  = reinterpret_cast<const float4*>(g_aggr2)[(size_t)i * 4 + q];
        float4 zv = reinterpret_cast<const float4*>(g_z)[(size_t)i * 4 + q];
        float4 bb = reinterpret_cast<const float4*>(b2)[q];
        l[q * 4 + 0] = a.x + s * zv.x + bb.x;
        l[q * 4 + 1] = a.y + s * zv.y + bb.y;
        l[q * 4 + 2] = a.z + s * zv.z + bb.z;
        l[q * 4 + 3] = a.w + s * zv.w + bb.w;
    }
    float m = l[0];
#pragma unroll
    for (int j = 1; j < 16; j++) m = fmaxf(m, l[j]);
    float sum = 0.f;
#pragma unroll
    for (int j = 0; j < 16; j++) sum += __expf(l[j] - m);
    float lse = m + __logf(sum);
#pragma unroll
    for (int q = 0; q < 4; q++) {
        float4 o;
        o.x = l[q * 4 + 0] - lse;
        o.y = l[q * 4 + 1] - lse;
        o.z = l[q * 4 + 2] - lse;
        o.w = l[q * 4 + 3] - lse;
        reinterpret_cast<float4*>(out)[(size_t)i * 4 + q] = o;
    }
}

// ---------------- launch ----------------
extern "C" void kernel_launch(void* const* d_in, const int* in_sizes, int n_in,
                              void* d_out, int out_size) {
    const float* x  = (const float*)d_in[0];
    const int*   ei = (const int*)d_in[1];   // JAX x64-disabled: int64 request -> int32 array
    const float* W1 = (const float*)d_in[2];
    const float* b1 = (const float*)d_in[3];
    const float* W2 = (const float*)d_in[4];
    const float* b2 = (const float*)d_in[5];
    float*       out = (float*)d_out;

    int N = in_sizes[0] / F_IN;
    int E = in_sizes[1] / 2;

    const int TB = 256;

    init_kernel<<<(N * 16 + TB - 1) / TB, TB>>>(N);
    deg_kernel<<<(E + TB - 1) / TB, TB>>>(ei, E);
    dinv_kernel<<<(N + TB - 1) / TB, TB>>>(N);
    edgeprep_kernel<<<(E + TB - 1) / TB, TB>>>(ei, E);

    gemm1_kernel<<<(N + 15) / 16, dim3(64, 4)>>>(x, W1, N);

    long long s1_threads = (long long)E * 16;
    scatter1_kernel<<<(unsigned)((s1_threads + TB - 1) / TB), TB>>>(E);

    epi1_kernel<<<(N * 16 + TB - 1) / TB, TB>>>(b1, N);

    gemm2_kernel<<<(N + 15) / 16, dim3(16, 16)>>>(W2, N);

    long long s2_threads = (long long)E * 4;
    scatter2_kernel<<<(unsigned)((s2_threads + TB - 1) / TB), TB>>>(E);

    epi2_kernel<<<(N + TB - 1) / TB, TB>>>(b2, out, N);
}

// round 3
// speedup vs baseline: 1.1406x; 1.1406x over previous
#include <cuda_runtime.h>
#include <math.h>

// ---------------- problem-size constants ----------------
#define MAXN 100000
#define MAXE 1200000
#define F_IN  64
#define F_HID 64
#define F_OUT 16
#define SCAN_B 256

// ---------------- device scratch ----------------
__device__ float g_y[MAXN * F_HID];      // x @ W1
__device__ float g_z[MAXN * F_OUT];      // h @ W2
__device__ int   g_deg[MAXN];            // out-degree by row (for dinv)
__device__ int   g_cnt[MAXN];            // in-degree by col (CSR counts)
__device__ float g_dinv[MAXN];
__device__ int   g_incl[MAXN];           // per-block inclusive scan of cnt
__device__ int   g_bsum[(MAXN + SCAN_B - 1) / SCAN_B];
__device__ int   g_bsumex[(MAXN + SCAN_B - 1) / SCAN_B];
__device__ int   g_start[MAXN];          // CSR row_ptr (exclusive scan)
__device__ int   g_cursor[MAXN];         // fill cursors
__device__ int2  g_edge[MAXE];           // packed (src, coef bits), sorted by col

// ---------------- kernels ----------------

__global__ void init0_kernel(int N) {
    int i = blockIdx.x * blockDim.x + threadIdx.x;
    if (i < N) { g_deg[i] = 0; g_cnt[i] = 0; }
}

// Histogram both endpoints in one pass.
__global__ void hist_kernel(const int* __restrict__ ei, int E) {
    int e = blockIdx.x * blockDim.x + threadIdx.x;
    if (e < E) {
        atomicAdd(&g_deg[ei[e]], 1);
        atomicAdd(&g_cnt[ei[E + e]], 1);
    }
}

__global__ void dinv_kernel(int N) {
    int i = blockIdx.x * blockDim.x + threadIdx.x;
    if (i < N) g_dinv[i] = rsqrtf((float)(g_deg[i] + 1));
}

// Per-block inclusive scan of g_cnt; block sums to g_bsum.
__global__ void scan1_kernel(int N) {
    __shared__ int s[SCAN_B];
    int t = threadIdx.x;
    int i = blockIdx.x * SCAN_B + t;
    int v = (i < N) ? g_cnt[i] : 0;
    s[t] = v;
    __syncthreads();
    for (int off = 1; off < SCAN_B; off <<= 1) {
        int u = (t >= off) ? s[t - off] : 0;
        __syncthreads();
        s[t] += u;
        __syncthreads();
    }
    if (i < N) g_incl[i] = s[t];
    if (t == SCAN_B - 1) g_bsum[blockIdx.x] = s[t];
}

// Exclusive scan of block sums (NB <= 512), single block.
__global__ void scan2_kernel(int NB) {
    __shared__ int s[512];
    int t = threadIdx.x;
    int v = (t < NB) ? g_bsum[t] : 0;
    s[t] = v;
    __syncthreads();
    for (int off = 1; off < 512; off <<= 1) {
        int u = (t >= off) ? s[t - off] : 0;
        __syncthreads();
        s[t] += u;
        __syncthreads();
    }
    if (t < NB) g_bsumex[t] = s[t] - v;
}

__global__ void scan3_kernel(int N) {
    int i = blockIdx.x * blockDim.x + threadIdx.x;
    if (i < N) {
        int st = g_incl[i] - g_cnt[i] + g_bsumex[i / SCAN_B];
        g_start[i] = st;
        g_cursor[i] = st;
    }
}

// Fill CSR: packed (src, coef) records bucketed by col.
__global__ void fill_kernel(const int* __restrict__ ei, int E) {
    int e = blockIdx.x * blockDim.x + threadIdx.x;
    if (e < E) {
        int r = ei[e];
        int c = ei[E + e];
        float coef = g_dinv[r] * g_dinv[c];
        int pos = atomicAdd(&g_cursor[c], 1);
        g_edge[pos] = make_int2(r, __float_as_int(coef));
    }
}

// y = x @ W1   ([N,64] @ [64,64])
__global__ __launch_bounds__(256) void gemm1_kernel(const float* __restrict__ x,
                                                    const float* __restrict__ W,
                                                    int N) {
    __shared__ float Ws[64 * 64];
    __shared__ float xs[16 * 64];
    int tx = threadIdx.x;           // 0..63 output column
    int ty = threadIdx.y;           // 0..3
    int tid = ty * 64 + tx;

    for (int i = tid; i < 64 * 64; i += 256) Ws[i] = W[i];

    int row0 = blockIdx.x * 16;
    {
        int r  = tid >> 4;
        int cc = tid & 15;
        int gr = row0 + r;
        float4 v = (gr < N) ? reinterpret_cast<const float4*>(x)[(size_t)gr * 16 + cc]
                            : make_float4(0.f, 0.f, 0.f, 0.f);
        reinterpret_cast<float4*>(xs)[r * 16 + cc] = v;
    }
    __syncthreads();

    float acc[4] = {0.f, 0.f, 0.f, 0.f};
#pragma unroll
    for (int k = 0; k < 64; k++) {
        float w = Ws[k * 64 + tx];
#pragma unroll
        for (int r = 0; r < 4; r++) acc[r] += xs[(ty * 4 + r) * 64 + k] * w;
    }
#pragma unroll
    for (int r = 0; r < 4; r++) {
        int gr = row0 + ty * 4 + r;
        if (gr < N) g_y[(size_t)gr * 64 + tx] = acc[r];
    }
}

// Fused: aggr1 (CSR gather) + self loop + bias + relu -> h (smem) -> z = h @ W2.
// One warp per node. 8 warps / 256-thread block.
__global__ __launch_bounds__(256) void agg1_kernel(const float* __restrict__ b1,
                                                   const float* __restrict__ W2,
                                                   int N) {
    __shared__ float W2s[64 * 16];
    __shared__ float h_sm[8][64];
    int tid = threadIdx.x;
    for (int i = tid; i < 64 * 16; i += 256) W2s[i] = W2[i];
    __syncthreads();

    int warp = (blockIdx.x * blockDim.x + tid) >> 5;
    if (warp >= N) return;
    int lane = tid & 31;
    int w = tid >> 5;

    int start = g_start[warp];
    int cnt = g_cnt[warp];
    int half = lane >> 4;     // which neighbor of the pair
    int q = lane & 15;        // float4 index within the 64-float row

    float4 acc = make_float4(0.f, 0.f, 0.f, 0.f);
    for (int j = half; j < cnt; j += 2) {
        int2 rec = g_edge[start + j];
        float coef = __int_as_float(rec.y);
        float4 v = reinterpret_cast<const float4*>(g_y)[(size_t)rec.x * 16 + q];
        acc.x += coef * v.x;
        acc.y += coef * v.y;
        acc.z += coef * v.z;
        acc.w += coef * v.w;
    }
    // combine the two halves
    acc.x += __shfl_down_sync(0xffffffffu, acc.x, 16);
    acc.y += __shfl_down_sync(0xffffffffu, acc.y, 16);
    acc.z += __shfl_down_sync(0xffffffffu, acc.z, 16);
    acc.w += __shfl_down_sync(0xffffffffu, acc.w, 16);

    if (lane < 16) {
        float di = g_dinv[warp];
        float s = di * di;
        float4 yv = reinterpret_cast<const float4*>(g_y)[(size_t)warp * 16 + q];
        float4 bb = reinterpret_cast<const float4*>(b1)[q];
        float4 hv;
        hv.x = fmaxf(acc.x + s * yv.x + bb.x, 0.f);
        hv.y = fmaxf(acc.y + s * yv.y + bb.y, 0.f);
        hv.z = fmaxf(acc.z + s * yv.z + bb.z, 0.f);
        hv.w = fmaxf(acc.w + s * yv.w + bb.w, 0.f);
        reinterpret_cast<float4*>(h_sm[w])[q] = hv;
    }
    __syncwarp();

    // z[warp] = h @ W2  (64 -> 16), lanes 0..15 each compute one output
    if (lane < 16) {
        float accz = 0.f;
#pragma unroll
        for (int k = 0; k < 64; k++) accz += h_sm[w][k] * W2s[k * 16 + lane];
        g_z[(size_t)warp * 16 + lane] = accz;
    }
}

// Fused: aggr2 (CSR gather) + self loop + bias + log_softmax -> out.
// One warp per node, 8 neighbors per iteration.
__global__ __launch_bounds__(256) void agg2_kernel(const float* __restrict__ b2,
                                                   float* __restrict__ out, int N) {
    int tid = threadIdx.x;
    int warp = (blockIdx.x * blockDim.x + tid) >> 5;
    if (warp >= N) return;
    int lane = tid & 31;

    int start = g_start[warp];
    int cnt = g_cnt[warp];
    int slot = lane >> 2;    // 0..7 neighbor slot
    int q = lane & 3;        // float4 index within the 16-float row

    float4 acc = make_float4(0.f, 0.f, 0.f, 0.f);
    for (int j = slot; j < cnt; j += 8) {
        int2 rec = g_edge[start + j];
        float coef = __int_as_float(rec.y);
        float4 v = reinterpret_cast<const float4*>(g_z)[(size_t)rec.x * 4 + q];
        acc.x += coef * v.x;
        acc.y += coef * v.y;
        acc.z += coef * v.z;
        acc.w += coef * v.w;
    }
    // butterfly-reduce across the 8 slots (offsets 4, 8, 16)
#pragma unroll
    for (int off = 4; off <= 16; off <<= 1) {
        acc.x += __shfl_xor_sync(0xffffffffu, acc.x, off);
        acc.y += __shfl_xor_sync(0xffffffffu, acc.y, off);
        acc.z += __shfl_xor_sync(0xffffffffu, acc.z, off);
        acc.w += __shfl_xor_sync(0xffffffffu, acc.w, off);
    }
    // every lane now holds the full sum for its q

    float di = g_dinv[warp];
    float s = di * di;
    float4 zv = reinterpret_cast<const float4*>(g_z)[(size_t)warp * 4 + q];
    float4 bb = reinterpret_cast<const float4*>(b2)[q];
    float4 l;
    l.x = acc.x + s * zv.x + bb.x;
    l.y = acc.y + s * zv.y + bb.y;
    l.z = acc.z + s * zv.z + bb.z;
    l.w = acc.w + s * zv.w + bb.w;

    // log_softmax over the 16 logits (4 q-lanes x 4 components)
    float m4 = fmaxf(fmaxf(l.x, l.y), fmaxf(l.z, l.w));
    m4 = fmaxf(m4, __shfl_xor_sync(0xffffffffu, m4, 1));
    m4 = fmaxf(m4, __shfl_xor_sync(0xffffffffu, m4, 2));
    float se = __expf(l.x - m4) + __expf(l.y - m4) + __expf(l.z - m4) + __expf(l.w - m4);
    se += __shfl_xor_sync(0xffffffffu, se, 1);
    se += __shfl_xor_sync(0xffffffffu, se, 2);
    float lse = m4 + __logf(se);

    if (lane < 4) {
        float4 o;
        o.x = l.x - lse;
        o.y = l.y - lse;
        o.z = l.z - lse;
        o.w = l.w - lse;
        reinterpret_cast<float4*>(out)[(size_t)warp * 4 + q] = o;
    }
}

// ---------------- launch ----------------
extern "C" void kernel_launch(void* const* d_in, const int* in_sizes, int n_in,
                              void* d_out, int out_size) {
    const float* x  = (const float*)d_in[0];
    const int*   ei = (const int*)d_in[1];   // int32 (JAX x64 disabled)
    const float* W1 = (const float*)d_in[2];
    const float* b1 = (const float*)d_in[3];
    const float* W2 = (const float*)d_in[4];
    const float* b2 = (const float*)d_in[5];
    float*       out = (float*)d_out;

    int N = in_sizes[0] / F_IN;
    int E = in_sizes[1] / 2;
    const int TB = 256;
    int NB = (N + SCAN_B - 1) / SCAN_B;

    init0_kernel<<<(N + TB - 1) / TB, TB>>>(N);
    hist_kernel<<<(E + TB - 1) / TB, TB>>>(ei, E);
    dinv_kernel<<<(N + TB - 1) / TB, TB>>>(N);
    scan1_kernel<<<NB, SCAN_B>>>(N);
    scan2_kernel<<<1, 512>>>(NB);
    scan3_kernel<<<(N + TB - 1) / TB, TB>>>(N);
    fill_kernel<<<(E + TB - 1) / TB, TB>>>(ei, E);

    gemm1_kernel<<<(N + 15) / 16, dim3(64, 4)>>>(x, W1, N);

    long long a1_threads = (long long)N * 32;
    agg1_kernel<<<(unsigned)((a1_threads + TB - 1) / TB), TB>>>(b1, W2, N);

    long long a2_threads = (long long)N * 32;
    agg2_kernel<<<(unsigned)((a2_threads + TB - 1) / TB), TB>>>(b2, out, N);
}

// round 4
// speedup vs baseline: 1.1682x; 1.0242x over previous
#include <cuda_runtime.h>
#include <cuda_fp16.h>
#include <math.h>

// ---------------- problem-size constants ----------------
#define MAXN 100000
#define MAXE 1200000
#define F_IN  64
#define F_HID 64
#define F_OUT 16
#define SCAN_B 256

// ---------------- device scratch ----------------
__device__ __half g_y_h[MAXN * F_HID];   // x @ W1, fp16
__device__ __half g_z_h[MAXN * F_OUT];   // h @ W2, fp16
__device__ int    g_deg[MAXN];           // out-degree by row (for dinv)
__device__ int    g_cnt[MAXN];           // in-degree by col (CSR counts)
__device__ float  g_dinv[MAXN];
__device__ int    g_incl[MAXN];          // per-block inclusive scan of cnt
__device__ int    g_bsum[(MAXN + SCAN_B - 1) / SCAN_B];
__device__ int    g_bsumex[(MAXN + SCAN_B - 1) / SCAN_B];
__device__ int    g_start[MAXN];         // CSR row_ptr (exclusive scan)
__device__ int    g_cursor[MAXN];        // fill cursors
__device__ int2   g_edge[MAXE];          // packed (src, coef bits), sorted by col

// ---------------- kernels ----------------

__global__ void init0_kernel(int N) {
    int i = blockIdx.x * blockDim.x + threadIdx.x;
    if (i < N) { g_deg[i] = 0; g_cnt[i] = 0; }
}

// Histogram both endpoints in one pass.
__global__ void hist_kernel(const int* __restrict__ ei, int E) {
    int e = blockIdx.x * blockDim.x + threadIdx.x;
    if (e < E) {
        atomicAdd(&g_deg[ei[e]], 1);
        atomicAdd(&g_cnt[ei[E + e]], 1);
    }
}

// Per-block inclusive scan of g_cnt; block sums to g_bsum. Also computes dinv.
__global__ void scan1_kernel(int N) {
    __shared__ int s[SCAN_B];
    int t = threadIdx.x;
    int i = blockIdx.x * SCAN_B + t;
    int v = (i < N) ? g_cnt[i] : 0;
    s[t] = v;
    if (i < N) g_dinv[i] = rsqrtf((float)(g_deg[i] + 1));
    __syncthreads();
    for (int off = 1; off < SCAN_B; off <<= 1) {
        int u = (t >= off) ? s[t - off] : 0;
        __syncthreads();
        s[t] += u;
        __syncthreads();
    }
    if (i < N) g_incl[i] = s[t];
    if (t == SCAN_B - 1) g_bsum[blockIdx.x] = s[t];
}

// Exclusive scan of block sums (NB <= 512), single block.
__global__ void scan2_kernel(int NB) {
    __shared__ int s[512];
    int t = threadIdx.x;
    int v = (t < NB) ? g_bsum[t] : 0;
    s[t] = v;
    __syncthreads();
    for (int off = 1; off < 512; off <<= 1) {
        int u = (t >= off) ? s[t - off] : 0;
        __syncthreads();
        s[t] += u;
        __syncthreads();
    }
    if (t < NB) g_bsumex[t] = s[t] - v;
}

__global__ void scan3_kernel(int N) {
    int i = blockIdx.x * blockDim.x + threadIdx.x;
    if (i < N) {
        int st = g_incl[i] - g_cnt[i] + g_bsumex[i / SCAN_B];
        g_start[i] = st;
        g_cursor[i] = st;
    }
}

// Fill CSR: packed (src, coef) records bucketed by col.
__global__ void fill_kernel(const int* __restrict__ ei, int E) {
    int e = blockIdx.x * blockDim.x + threadIdx.x;
    if (e < E) {
        int r = ei[e];
        int c = ei[E + e];
        float coef = g_dinv[r] * g_dinv[c];
        int pos = atomicAdd(&g_cursor[c], 1);
        g_edge[pos] = make_int2(r, __float_as_int(coef));
    }
}

// y = x @ W1   ([N,64] @ [64,64]) -> fp16 output
__global__ __launch_bounds__(256) void gemm1_kernel(const float* __restrict__ x,
                                                    const float* __restrict__ W,
                                                    int N) {
    __shared__ float Ws[64 * 64];
    __shared__ float xs[16 * 64];
    int tx = threadIdx.x;           // 0..63 output column
    int ty = threadIdx.y;           // 0..3
    int tid = ty * 64 + tx;

    for (int i = tid; i < 64 * 64; i += 256) Ws[i] = W[i];

    int row0 = blockIdx.x * 16;
    {
        int r  = tid >> 4;
        int cc = tid & 15;
        int gr = row0 + r;
        float4 v = (gr < N) ? reinterpret_cast<const float4*>(x)[(size_t)gr * 16 + cc]
                            : make_float4(0.f, 0.f, 0.f, 0.f);
        reinterpret_cast<float4*>(xs)[r * 16 + cc] = v;
    }
    __syncthreads();

    float acc[4] = {0.f, 0.f, 0.f, 0.f};
#pragma unroll
    for (int k = 0; k < 64; k++) {
        float w = Ws[k * 64 + tx];
#pragma unroll
        for (int r = 0; r < 4; r++) acc[r] += xs[(ty * 4 + r) * 64 + k] * w;
    }
    // pack pairs of adjacent columns into half2 (even lane writes)
#pragma unroll
    for (int r = 0; r < 4; r++) {
        float other = __shfl_xor_sync(0xffffffffu, acc[r], 1);
        int gr = row0 + ty * 4 + r;
        if ((tx & 1) == 0 && gr < N) {
            __half2 hv = __floats2half2_rn(acc[r], other);
            reinterpret_cast<__half2*>(g_y_h)[(size_t)gr * 32 + (tx >> 1)] = hv;
        }
    }
}

// Fused: aggr1 (CSR gather of fp16 rows) + self loop + bias + relu -> h (smem)
//        -> z = h @ W2 -> fp16.
// One warp per node; 4 neighbors in flight (8 lanes x uint4 each).
__global__ __launch_bounds__(256) void agg1_kernel(const float* __restrict__ b1,
                                                   const float* __restrict__ W2,
                                                   int N) {
    __shared__ float W2s[64 * 16];
    __shared__ float h_sm[8][64];
    int tid = threadIdx.x;
    for (int i = tid; i < 64 * 16; i += 256) W2s[i] = W2[i];
    __syncthreads();

    int warp = (blockIdx.x * blockDim.x + tid) >> 5;
    if (warp >= N) return;
    int lane = tid & 31;
    int w = tid >> 5;

    int start = g_start[warp];
    int cnt = g_cnt[warp];
    int slot = lane >> 3;     // 0..3 neighbor slot
    int q = lane & 7;         // uint4 (8-half) chunk within 128B row

    float a[8];
#pragma unroll
    for (int i = 0; i < 8; i++) a[i] = 0.f;

    const uint4* yrows = reinterpret_cast<const uint4*>(g_y_h);
    for (int j = slot; j < cnt; j += 4) {
        int2 rec = g_edge[start + j];
        float coef = __int_as_float(rec.y);
        uint4 v = yrows[(size_t)rec.x * 8 + q];
        float2 f0 = __half22float2(*reinterpret_cast<__half2*>(&v.x));
        float2 f1 = __half22float2(*reinterpret_cast<__half2*>(&v.y));
        float2 f2 = __half22float2(*reinterpret_cast<__half2*>(&v.z));
        float2 f3 = __half22float2(*reinterpret_cast<__half2*>(&v.w));
        a[0] += coef * f0.x;  a[1] += coef * f0.y;
        a[2] += coef * f1.x;  a[3] += coef * f1.y;
        a[4] += coef * f2.x;  a[5] += coef * f2.y;
        a[6] += coef * f3.x;  a[7] += coef * f3.y;
    }
    // reduce across the 4 slots
#pragma unroll
    for (int i = 0; i < 8; i++) {
        a[i] += __shfl_xor_sync(0xffffffffu, a[i], 8);
        a[i] += __shfl_xor_sync(0xffffffffu, a[i], 16);
    }

    if (lane < 8) {
        float di = g_dinv[warp];
        float s = di * di;
        uint4 yv = yrows[(size_t)warp * 8 + q];
        float2 y0 = __half22float2(*reinterpret_cast<__half2*>(&yv.x));
        float2 y1 = __half22float2(*reinterpret_cast<__half2*>(&yv.y));
        float2 y2 = __half22float2(*reinterpret_cast<__half2*>(&yv.z));
        float2 y3 = __half22float2(*reinterpret_cast<__half2*>(&yv.w));
        float4 bb0 = reinterpret_cast<const float4*>(b1)[q * 2];
        float4 bb1 = reinterpret_cast<const float4*>(b1)[q * 2 + 1];
        float4 h0, h1;
        h0.x = fmaxf(a[0] + s * y0.x + bb0.x, 0.f);
        h0.y = fmaxf(a[1] + s * y0.y + bb0.y, 0.f);
        h0.z = fmaxf(a[2] + s * y1.x + bb0.z, 0.f);
        h0.w = fmaxf(a[3] + s * y1.y + bb0.w, 0.f);
        h1.x = fmaxf(a[4] + s * y2.x + bb1.x, 0.f);
        h1.y = fmaxf(a[5] + s * y2.y + bb1.y, 0.f);
        h1.z = fmaxf(a[6] + s * y3.x + bb1.z, 0.f);
        h1.w = fmaxf(a[7] + s * y3.y + bb1.w, 0.f);
        reinterpret_cast<float4*>(h_sm[w])[q * 2]     = h0;
        reinterpret_cast<float4*>(h_sm[w])[q * 2 + 1] = h1;
    }
    __syncwarp();

    // z[warp] = h @ W2  (64 -> 16), lanes 0..15 each compute one output
    float accz = 0.f;
    if (lane < 16) {
#pragma unroll
        for (int k = 0; k < 64; k++) accz += h_sm[w][k] * W2s[k * 16 + lane];
    }
    // pack adjacent outputs into half2 (even lanes write)
    float otherz = __shfl_xor_sync(0xffffffffu, accz, 1);
    if (lane < 16 && (lane & 1) == 0) {
        __half2 hz = __floats2half2_rn(accz, otherz);
        reinterpret_cast<__half2*>(g_z_h)[(size_t)warp * 8 + (lane >> 1)] = hz;
    }
}

// Fused: aggr2 (CSR gather of fp16 rows) + self loop + bias + log_softmax -> out.
// One warp per node; 8 neighbors in flight (4 lanes x uint2 each).
__global__ __launch_bounds__(256) void agg2_kernel(const float* __restrict__ b2,
                                                   float* __restrict__ out, int N) {
    int tid = threadIdx.x;
    int warp = (blockIdx.x * blockDim.x + tid) >> 5;
    if (warp >= N) return;
    int lane = tid & 31;

    int start = g_start[warp];
    int cnt = g_cnt[warp];
    int slot = lane >> 2;    // 0..7 neighbor slot
    int q = lane & 3;        // uint2 (4-half) chunk within 32B row

    float a[4];
#pragma unroll
    for (int i = 0; i < 4; i++) a[i] = 0.f;

    const uint2* zrows = reinterpret_cast<const uint2*>(g_z_h);
    for (int j = slot; j < cnt; j += 8) {
        int2 rec = g_edge[start + j];
        float coef = __int_as_float(rec.y);
        uint2 v = zrows[(size_t)rec.x * 4 + q];
        float2 f0 = __half22float2(*reinterpret_cast<__half2*>(&v.x));
        float2 f1 = __half22float2(*reinterpret_cast<__half2*>(&v.y));
        a[0] += coef * f0.x;  a[1] += coef * f0.y;
        a[2] += coef * f1.x;  a[3] += coef * f1.y;
    }
#pragma unroll
    for (int i = 0; i < 4; i++) {
        a[i] += __shfl_xor_sync(0xffffffffu, a[i], 4);
        a[i] += __shfl_xor_sync(0xffffffffu, a[i], 8);
        a[i] += __shfl_xor_sync(0xffffffffu, a[i], 16);
    }
    // every lane now holds the full sum for its q

    float di = g_dinv[warp];
    float s = di * di;
    uint2 zv = zrows[(size_t)warp * 4 + q];
    float2 z0 = __half22float2(*reinterpret_cast<__half2*>(&zv.x));
    float2 z1 = __half22float2(*reinterpret_cast<__half2*>(&zv.y));
    float4 bb = reinterpret_cast<const float4*>(b2)[q];
    float4 l;
    l.x = a[0] + s * z0.x + bb.x;
    l.y = a[1] + s * z0.y + bb.y;
    l.z = a[2] + s * z1.x + bb.z;
    l.w = a[3] + s * z1.y + bb.w;

    // log_softmax over the 16 logits (4 q-lanes x 4 components)
    float m4 = fmaxf(fmaxf(l.x, l.y), fmaxf(l.z, l.w));
    m4 = fmaxf(m4, __shfl_xor_sync(0xffffffffu, m4, 1));
    m4 = fmaxf(m4, __shfl_xor_sync(0xffffffffu, m4, 2));
    float se = __expf(l.x - m4) + __expf(l.y - m4) + __expf(l.z - m4) + __expf(l.w - m4);
    se += __shfl_xor_sync(0xffffffffu, se, 1);
    se += __shfl_xor_sync(0xffffffffu, se, 2);
    float lse = m4 + __logf(se);

    if (lane < 4) {
        float4 o;
        o.x = l.x - lse;
        o.y = l.y - lse;
        o.z = l.z - lse;
        o.w = l.w - lse;
        reinterpret_cast<float4*>(out)[(size_t)warp * 4 + q] = o;
    }
}

// ---------------- launch ----------------
extern "C" void kernel_launch(void* const* d_in, const int* in_sizes, int n_in,
                              void* d_out, int out_size) {
    const float* x  = (const float*)d_in[0];
    const int*   ei = (const int*)d_in[1];   // int32 (JAX x64 disabled)
    const float* W1 = (const float*)d_in[2];
    const float* b1 = (const float*)d_in[3];
    const float* W2 = (const float*)d_in[4];
    const float* b2 = (const float*)d_in[5];
    float*       out = (float*)d_out;

    int N = in_sizes[0] / F_IN;
    int E = in_sizes[1] / 2;
    const int TB = 256;
    int NB = (N + SCAN_B - 1) / SCAN_B;

    init0_kernel<<<(N + TB - 1) / TB, TB>>>(N);
    hist_kernel<<<(E + TB - 1) / TB, TB>>>(ei, E);
    scan1_kernel<<<NB, SCAN_B>>>(N);
    scan2_kernel<<<1, 512>>>(NB);
    scan3_kernel<<<(N + TB - 1) / TB, TB>>>(N);
    fill_kernel<<<(E + TB - 1) / TB, TB>>>(ei, E);

    gemm1_kernel<<<(N + 15) / 16, dim3(64, 4)>>>(x, W1, N);

    long long a1_threads = (long long)N * 32;
    agg1_kernel<<<(unsigned)((a1_threads + TB - 1) / TB), TB>>>(b1, W2, N);

    long long a2_threads = (long long)N * 32;
    agg2_kernel<<<(unsigned)((a2_threads + TB - 1) / TB), TB>>>(b2, out, N);
}